// round 5
// baseline (speedup 1.0000x reference)
#include <cuda_runtime.h>
#include <cuda_fp16.h>
#include <cstdint>

typedef unsigned long long ull;

namespace {
constexpr int Bsz = 32768, Adim = 8, Hdim = 256, NSTEPS = 50;
constexpr int TB = 64, NT = 512;
constexpr float DTC = 1.0f / 50.0f;

// byte offsets within 1024-aligned smem base
constexpr int OFF_X   = 0;        // 65536: X f16 [128 rows][256 k] blocked swizzle (setup: c_base f32 [64][256])
constexpr int OFF_W2T = 65536;    // 131072: W2^T f16 [256 n][256 k] blocked swizzle (setup: feats f32 [64][260])
constexpr int OFF_VP  = 196608;   // 8192: v partials [4][64][8] f32 (setup: wst [16][256] spans VP+JP)
constexpr int OFF_JP  = 204800;   // 8192: jv partials
constexpr int OFF_W3  = 212992;   // 8192: W3 [256][8] f32
constexpr int OFF_B2  = 221184;   // 1024
constexpr int OFF_AS  = 222208;   // 2048: a_s [64][8]
constexpr int OFF_ES  = 224256;   // 2048: e_s [64][8]
constexpr int OFF_DI  = 226304;   // 256
constexpr int SMEM_BYTES = 226560 + 1024;
}  // namespace

__device__ __forceinline__ uint32_t cvta_smem(const void* p) {
    uint32_t a;
    asm("{ .reg .u64 t; cvta.to.shared.u64 t, %1; cvt.u32.u64 %0, t; }" : "=r"(a) : "l"(p));
    return a;
}
__device__ __forceinline__ uint32_t swz(uint32_t o) { return o ^ ((o >> 3) & 0x70u); }
// blocked K-major layouts: atom = 8 rows x 128B (64 f16); atoms advance row-major then k-block
__device__ __forceinline__ uint32_t xbyte(int row, int k) {   // X: 128 rows
    return (uint32_t)((((row >> 3) + ((k >> 6) << 4)) << 10) + ((row & 7) << 7) + ((k & 63) << 1));
}
__device__ __forceinline__ ull pack2(float x) { ull r; asm("mov.b64 %0,{%1,%1};" : "=l"(r) : "f"(x)); return r; }
__device__ __forceinline__ void fma2(ull& d, ull a, ull b) { asm("fma.rn.f32x2 %0,%1,%2,%0;" : "+l"(d) : "l"(a), "l"(b)); }
__device__ __forceinline__ void unpack2(ull v, float& lo, float& hi) { asm("mov.b64 {%0,%1},%2;" : "=f"(lo), "=f"(hi) : "l"(v)); }

__device__ __forceinline__ void ldsm4(uint32_t& r0, uint32_t& r1, uint32_t& r2, uint32_t& r3, uint32_t a) {
    asm volatile("ldmatrix.sync.aligned.m8n8.x4.shared.b16 {%0,%1,%2,%3}, [%4];"
                 : "=r"(r0), "=r"(r1), "=r"(r2), "=r"(r3) : "r"(a));
}
__device__ __forceinline__ void mma16816(float* c, uint32_t a0, uint32_t a1, uint32_t a2, uint32_t a3,
                                         uint32_t b0, uint32_t b1) {
    asm volatile("mma.sync.aligned.m16n8k16.row.col.f32.f16.f16.f32 "
                 "{%0,%1,%2,%3}, {%4,%5,%6,%7}, {%8,%9}, {%0,%1,%2,%3};"
                 : "+f"(c[0]), "+f"(c[1]), "+f"(c[2]), "+f"(c[3])
                 : "r"(a0), "r"(a1), "r"(a2), "r"(a3), "r"(b0), "r"(b1));
}

__global__ void __launch_bounds__(NT, 1) fm_logp_kernel(
    const float* __restrict__ actions, const float* __restrict__ feats,
    const float* __restrict__ W1, const float* __restrict__ b1,
    const float* __restrict__ W2, const float* __restrict__ b2g,
    const float* __restrict__ W3g, const float* __restrict__ b3g,
    const float* __restrict__ eps, float* __restrict__ out)
{
    extern __shared__ char smraw[];
    const uint32_t base0 = cvta_smem(smraw);
    const uint32_t smb = (base0 + 1023u) & ~1023u;
    char* smc = smraw + (smb - base0);

    float* vp_s = (float*)(smc + OFF_VP);
    float* jp_s = (float*)(smc + OFF_JP);
    float* w3s  = (float*)(smc + OFF_W3);
    float* b2s  = (float*)(smc + OFF_B2);
    float* a_s  = (float*)(smc + OFF_AS);
    float* e_s  = (float*)(smc + OFF_ES);
    float* di_s = (float*)(smc + OFF_DI);

    const int tid  = threadIdx.x;
    const int lane = tid & 31;
    const int warp = tid >> 5;
    const int row0 = blockIdx.x * TB;

    // ================= setup: c_base = feats @ W1[8:264] + b1 (fp32, one-time) =================
    {
        float* featss = (float*)(smc + OFF_W2T);  // [64][260]
        float* wstp   = (float*)(smc + OFF_VP);   // [16][256] (spans VP+JP)
        float* cb32   = (float*)(smc + OFF_X);    // [64][256]

        for (int idx = tid; idx < TB * Hdim; idx += NT)
            featss[(idx >> 8) * 260 + (idx & 255)] = feats[row0 * Hdim + idx];
        if (tid < TB * Adim) a_s[tid] = actions[row0 * Adim + tid];
        if (tid < TB) di_s[tid] = 0.0f;
        __syncthreads();

        const int wr0 = warp * 4, jb = lane * 8;
        ull acc[4][4];
        #pragma unroll
        for (int r = 0; r < 4; r++)
            #pragma unroll
            for (int c = 0; c < 4; c++) acc[r][c] = 0ull;

        for (int kb = 0; kb < Hdim; kb += 16) {
            __syncthreads();
            {
                int i = tid;      int rr = i >> 6, cf = (i & 63) << 2;
                *(float4*)&wstp[rr * 256 + cf] = *(const float4*)&W1[(Adim + kb + rr) * Hdim + cf];
                i = tid + NT;     rr = i >> 6;  cf = (i & 63) << 2;
                *(float4*)&wstp[rr * 256 + cf] = *(const float4*)&W1[(Adim + kb + rr) * Hdim + cf];
            }
            __syncthreads();
            #pragma unroll
            for (int kk = 0; kk < 16; kk += 4) {
                float hb[4][4];
                #pragma unroll
                for (int r = 0; r < 4; r++)
                    *(float4*)hb[r] = *(const float4*)&featss[(wr0 + r) * 260 + kb + kk];
                #pragma unroll
                for (int j = 0; j < 4; j++) {
                    const float* wr_ = &wstp[(kk + j) * 256 + jb];
                    ulonglong2 w01 = *(const ulonglong2*)wr_;
                    ulonglong2 w23 = *(const ulonglong2*)(wr_ + 4);
                    #pragma unroll
                    for (int r = 0; r < 4; r++) {
                        ull hp = pack2(hb[r][j]);
                        fma2(acc[r][0], hp, w01.x); fma2(acc[r][1], hp, w01.y);
                        fma2(acc[r][2], hp, w23.x); fma2(acc[r][3], hp, w23.y);
                    }
                }
            }
        }
        __syncthreads();
        float4 bb0 = *(const float4*)&b1[jb];
        float4 bb1 = *(const float4*)&b1[jb + 4];
        #pragma unroll
        for (int r = 0; r < 4; r++) {
            float o[8];
            unpack2(acc[r][0], o[0], o[1]); unpack2(acc[r][1], o[2], o[3]);
            unpack2(acc[r][2], o[4], o[5]); unpack2(acc[r][3], o[6], o[7]);
            o[0] += bb0.x; o[1] += bb0.y; o[2] += bb0.z; o[3] += bb0.w;
            o[4] += bb1.x; o[5] += bb1.y; o[6] += bb1.z; o[7] += bb1.w;
            *(float4*)&cb32[(wr0 + r) * 256 + jb]     = make_float4(o[0], o[1], o[2], o[3]);
            *(float4*)&cb32[(wr0 + r) * 256 + jb + 4] = make_float4(o[4], o[5], o[6], o[7]);
        }
        __syncthreads();
    }

    // ---- per-thread persistent state ----
    const int c2 = (tid & 127) * 2;   // phase-A column pair
    const int rh = tid >> 7;          // 0..3 : rows rh, rh+4, ...
    float2 cb[16];
    {
        const float* cb32 = (const float*)(smc + OFF_X);
        #pragma unroll
        for (int j = 0; j < 16; j++)
            cb[j] = *(const float2*)&cb32[(rh + 4 * j) * 256 + c2];
    }
    __syncthreads();   // X region free for the f16 tile now

    float w1a2[Adim][2], w1t2[2];
    #pragma unroll
    for (int k = 0; k < Adim; k++) {
        w1a2[k][0] = W1[k * Hdim + c2];
        w1a2[k][1] = W1[k * Hdim + c2 + 1];
    }
    w1t2[0] = W1[(Adim + Hdim) * Hdim + c2];
    w1t2[1] = W1[(Adim + Hdim) * Hdim + c2 + 1];
    const float b3_r = b3g[tid & 7];

    // ---- W2^T f16 swizzled [n][k], W3, b2 into smem ----
    for (int idx = tid; idx < Hdim * Hdim; idx += NT) {
        int k = idx >> 8, n = idx & 255;
        uint32_t byte = (uint32_t)((((n >> 3) + ((k >> 6) << 5)) << 10) + ((n & 7) << 7) + ((k & 63) << 1));
        *(__half*)(smc + OFF_W2T + swz(byte)) = __float2half_rn(W2[idx]);
    }
    for (int idx = tid; idx < Hdim * Adim; idx += NT) w3s[idx] = W3g[idx];
    if (tid < Hdim) b2s[tid] = b2g[tid];
    __syncthreads();

    // ---- warp tiling + ldmatrix base offsets ----
    const int m0 = (warp >> 2) * 32;        // X row base (32 rows)
    const int n0 = (warp & 3) * 64;         // output col base (64 cols)
    const int rowA = m0 + ((lane >> 3) & 1) * 8 + (lane & 7);
    const int kA0  = (lane >> 4) * 8;
    uint32_t aoff0 = smb + OFF_X + (((uint32_t)(rowA >> 3)) << 10) + (((uint32_t)(rowA & 7)) << 7)
                   + ((uint32_t)kA0 << 1);
    aoff0 ^= ((uint32_t)(rowA & 7)) << 4;
    const int nB  = n0 + ((lane >> 4) & 1) * 8 + (lane & 7);
    const int kB0 = ((lane >> 3) & 1) * 8;
    uint32_t boff0 = smb + OFF_W2T + (((uint32_t)(nB >> 3)) << 10) + (((uint32_t)(nB & 7)) << 7)
                   + ((uint32_t)kB0 << 1);
    boff0 ^= ((uint32_t)(nB & 7)) << 4;

    const bool zrow = ((lane >> 2) & 1) == 0;          // even X row => h (value) row
    const int  br0  = (m0 >> 1) + ((lane >> 2) >> 1);  // batch row base for epilogue slots
    const float4* pa = (const float4*)a_s;
    const float4* pe = (const float4*)e_s;

    // ================= 50 reverse-Euler steps =================
    for (int step = 0; step < NSTEPS; step++) {
        const float tcur = 1.0f - (float)step * DTC;

        __syncthreads();
        e_s[tid] = eps[(size_t)step * Bsz * Adim + row0 * Adim + tid];
        __syncthreads();

        // ---- phase A: layer-1 value+tangent, silu, write X f16 (rows 2r=h, 2r+1=g) ----
        #pragma unroll
        for (int j = 0; j < 16; j++) {
            const int r = rh + 4 * j;
            float4 a0 = pa[2 * r], a1 = pa[2 * r + 1];
            float4 e0 = pe[2 * r], e1 = pe[2 * r + 1];
            float av[8] = {a0.x, a0.y, a0.z, a0.w, a1.x, a1.y, a1.z, a1.w};
            float ev[8] = {e0.x, e0.y, e0.z, e0.w, e1.x, e1.y, e1.z, e1.w};
            float z0 = cb[j].x + tcur * w1t2[0];
            float z1 = cb[j].y + tcur * w1t2[1];
            float d0 = 0.f, d1 = 0.f;
            #pragma unroll
            for (int k = 0; k < Adim; k++) {
                z0 += av[k] * w1a2[k][0];  z1 += av[k] * w1a2[k][1];
                d0 += ev[k] * w1a2[k][0];  d1 += ev[k] * w1a2[k][1];
            }
            float s0 = 1.0f / (1.0f + __expf(-z0));
            float s1 = 1.0f / (1.0f + __expf(-z1));
            float h0 = z0 * s0, h1v = z1 * s1;
            float g0 = d0 * (s0 * (1.0f + z0 * (1.0f - s0)));
            float g1v = d1 * (s1 * (1.0f + z1 * (1.0f - s1)));
            *(__half2*)(smc + OFF_X + swz(xbyte(2 * r,     c2))) = __floats2half2_rn(h0, h1v);
            *(__half2*)(smc + OFF_X + swz(xbyte(2 * r + 1, c2))) = __floats2half2_rn(g0, g1v);
        }
        __syncthreads();

        // ---- GEMM: D[32x64 per warp] = X @ W2T^T via mma.sync m16n8k16 ----
        float acc[2][8][4];
        #pragma unroll
        for (int mt = 0; mt < 2; mt++)
            #pragma unroll
            for (int nt = 0; nt < 8; nt++)
                #pragma unroll
                for (int i = 0; i < 4; i++) acc[mt][nt][i] = 0.0f;

        #pragma unroll
        for (int kc = 0; kc < 16; kc++) {
            const uint32_t klo = ((uint32_t)(kc & 3)) << 5;
            uint32_t ka = (aoff0 + (((uint32_t)(kc >> 2)) << 14)) ^ klo;
            uint32_t a00, a01, a02, a03, a10, a11, a12, a13;
            ldsm4(a00, a01, a02, a03, ka);
            ldsm4(a10, a11, a12, a13, ka + 2048);   // rows +16
            uint32_t kb = (boff0 + (((uint32_t)(kc >> 2)) << 15)) ^ klo;
            #pragma unroll
            for (int p = 0; p < 4; p++) {
                uint32_t b0, b1, b2r, b3r;
                ldsm4(b0, b1, b2r, b3r, kb + (uint32_t)p * 2048);   // n-tiles 2p, 2p+1
                mma16816(acc[0][2 * p],     a00, a01, a02, a03, b0, b1);
                mma16816(acc[0][2 * p + 1], a00, a01, a02, a03, b2r, b3r);
                mma16816(acc[1][2 * p],     a10, a11, a12, a13, b0, b1);
                mma16816(acc[1][2 * p + 1], a10, a11, a12, a13, b2r, b3r);
            }
        }

        // ---- epilogue (registers): silu'(z2) pairing via shfl, project through W3 ----
        {
            float vj[4][8];
            #pragma unroll
            for (int s = 0; s < 4; s++)
                #pragma unroll
                for (int i = 0; i < 8; i++) vj[s][i] = 0.0f;

            #pragma unroll
            for (int nt = 0; nt < 8; nt++) {
                const int colb = n0 + nt * 8 + (lane & 3) * 2;
                const float b2a = b2s[colb], b2b = b2s[colb + 1];
                float ct[4][2];
                #pragma unroll
                for (int mt = 0; mt < 2; mt++) {
                    float v0 = acc[mt][nt][0], v1 = acc[mt][nt][1];
                    float v2 = acc[mt][nt][2], v3 = acc[mt][nt][3];
                    float z0 = v0 + b2a, z1 = v1 + b2b, z2 = v2 + b2a, z3 = v3 + b2b;
                    float s0 = 1.0f / (1.0f + __expf(-z0));
                    float s1 = 1.0f / (1.0f + __expf(-z1));
                    float s2 = 1.0f / (1.0f + __expf(-z2));
                    float s3 = 1.0f / (1.0f + __expf(-z3));
                    float dc0 = s0 * (1.0f + z0 * (1.0f - s0));
                    float dc1 = s1 * (1.0f + z1 * (1.0f - s1));
                    float dc2 = s2 * (1.0f + z2 * (1.0f - s2));
                    float dc3 = s3 * (1.0f + z3 * (1.0f - s3));
                    float r0 = __shfl_up_sync(0xffffffffu, dc0, 4);
                    float r1 = __shfl_up_sync(0xffffffffu, dc1, 4);
                    float r2 = __shfl_up_sync(0xffffffffu, dc2, 4);
                    float r3 = __shfl_up_sync(0xffffffffu, dc3, 4);
                    ct[mt * 2 + 0][0] = zrow ? z0 * s0 : v0 * r0;
                    ct[mt * 2 + 0][1] = zrow ? z1 * s1 : v1 * r1;
                    ct[mt * 2 + 1][0] = zrow ? z2 * s2 : v2 * r2;
                    ct[mt * 2 + 1][1] = zrow ? z3 * s3 : v3 * r3;
                }
                float4 wa0 = *(const float4*)&w3s[colb * 8];
                float4 wa1 = *(const float4*)&w3s[colb * 8 + 4];
                float4 wb0 = *(const float4*)&w3s[(colb + 1) * 8];
                float4 wb1 = *(const float4*)&w3s[(colb + 1) * 8 + 4];
                #pragma unroll
                for (int s = 0; s < 4; s++) {
                    vj[s][0] += ct[s][0] * wa0.x + ct[s][1] * wb0.x;
                    vj[s][1] += ct[s][0] * wa0.y + ct[s][1] * wb0.y;
                    vj[s][2] += ct[s][0] * wa0.z + ct[s][1] * wb0.z;
                    vj[s][3] += ct[s][0] * wa0.w + ct[s][1] * wb0.w;
                    vj[s][4] += ct[s][0] * wa1.x + ct[s][1] * wb1.x;
                    vj[s][5] += ct[s][0] * wa1.y + ct[s][1] * wb1.y;
                    vj[s][6] += ct[s][0] * wa1.z + ct[s][1] * wb1.z;
                    vj[s][7] += ct[s][0] * wa1.w + ct[s][1] * wb1.w;
                }
            }
            // reduce over the 4 lanes of each quad (same row, different col pairs)
            #pragma unroll
            for (int s = 0; s < 4; s++)
                #pragma unroll
                for (int i = 0; i < 8; i++) {
                    vj[s][i] += __shfl_xor_sync(0xffffffffu, vj[s][i], 1);
                    vj[s][i] += __shfl_xor_sync(0xffffffffu, vj[s][i], 2);
                }
            if ((lane & 3) == 0) {
                float* dst = (zrow ? vp_s : jp_s) + (warp & 3) * 512;
                #pragma unroll
                for (int s = 0; s < 4; s++) {
                    const int row = br0 + (s & 1) * 4 + (s >> 1) * 8;
                    *(float4*)&dst[row * 8]     = make_float4(vj[s][0], vj[s][1], vj[s][2], vj[s][3]);
                    *(float4*)&dst[row * 8 + 4] = make_float4(vj[s][4], vj[s][5], vj[s][6], vj[s][7]);
                }
            }
        }
        __syncthreads();

        // ---- update: reduce 4 n-groups, Euler step, divergence integral ----
        {
            const int ur = tid >> 3, ui = tid & 7;
            float v = b3_r, jv = 0.0f;
            #pragma unroll
            for (int g = 0; g < 4; g++) {
                v  += vp_s[g * 512 + ur * 8 + ui];
                jv += jp_s[g * 512 + ur * 8 + ui];
            }
            float dp = jv * e_s[ur * 8 + ui];
            dp += __shfl_xor_sync(0xffffffffu, dp, 1);
            dp += __shfl_xor_sync(0xffffffffu, dp, 2);
            dp += __shfl_xor_sync(0xffffffffu, dp, 4);
            a_s[ur * 8 + ui] -= v * DTC;
            if (ui == 0) di_s[ur] += dp * DTC;
        }
    }

    // ================= output =================
    __syncthreads();
    if (tid < TB) {
        float s2 = 0.0f;
        #pragma unroll
        for (int i = 0; i < Adim; i++) {
            float av = a_s[tid * Adim + i];
            s2 += av * av;
        }
        out[row0 + tid] = -0.5f * (s2 + (float)Adim * 1.8378770664093453f) - di_s[tid];
    }
}

extern "C" void kernel_launch(void* const* d_in, const int* in_sizes, int n_in,
                              void* d_out, int out_size) {
    (void)in_sizes; (void)n_in; (void)out_size;
    cudaFuncSetAttribute(fm_logp_kernel,
                         cudaFuncAttributeMaxDynamicSharedMemorySize, SMEM_BYTES);
    fm_logp_kernel<<<Bsz / TB, NT, SMEM_BYTES>>>(
        (const float*)d_in[0], (const float*)d_in[1], (const float*)d_in[2],
        (const float*)d_in[3], (const float*)d_in[4], (const float*)d_in[5],
        (const float*)d_in[6], (const float*)d_in[7], (const float*)d_in[8],
        (float*)d_out);
}

// round 6
// speedup vs baseline: 1.0011x; 1.0011x over previous
#include <cuda_runtime.h>
#include <cuda_fp16.h>
#include <cstdint>

typedef unsigned long long ull;

namespace {
constexpr int Bsz = 32768, Adim = 8, Hdim = 256, NSTEPS = 50;
constexpr int TB = 64, NT = 512;
constexpr float DTC = 1.0f / 50.0f;

// byte offsets within 1024-aligned smem base
constexpr int OFF_X   = 0;        // 65536: X f16 [128 rows][256 k] blocked swizzle (setup: c_base f32 [64][256])
constexpr int OFF_W2T = 65536;    // 131072: W2^T f16 [256 n][256 k] blocked swizzle (setup: feats f32 [64][260])
constexpr int OFF_VP  = 196608;   // 8192: v partials [4][64][8] f32 (setup: wst [16][256] spans VP+JP)
constexpr int OFF_JP  = 204800;   // 8192: jv partials
constexpr int OFF_W3  = 212992;   // 8192: W3 [256][8] f32
constexpr int OFF_B2  = 221184;   // 1024
constexpr int OFF_AS  = 222208;   // 2048: a_s [64][8]
constexpr int OFF_ES  = 224256;   // 2048: e_s [64][8]
constexpr int OFF_DI  = 226304;   // 256
constexpr int SMEM_BYTES = 226560 + 1024;
}  // namespace

__device__ __forceinline__ uint32_t cvta_smem(const void* p) {
    uint32_t a;
    asm("{ .reg .u64 t; cvta.to.shared.u64 t, %1; cvt.u32.u64 %0, t; }" : "=r"(a) : "l"(p));
    return a;
}
__device__ __forceinline__ uint32_t swz(uint32_t o) { return o ^ ((o >> 3) & 0x70u); }
// blocked K-major layouts: atom = 8 rows x 128B (64 f16); atoms advance row-major then k-block
__device__ __forceinline__ uint32_t xbyte(int row, int k) {   // X: 128 rows
    return (uint32_t)((((row >> 3) + ((k >> 6) << 4)) << 10) + ((row & 7) << 7) + ((k & 63) << 1));
}
__device__ __forceinline__ ull pack2(float x) { ull r; asm("mov.b64 %0,{%1,%1};" : "=l"(r) : "f"(x)); return r; }
__device__ __forceinline__ void fma2(ull& d, ull a, ull b) { asm("fma.rn.f32x2 %0,%1,%2,%0;" : "+l"(d) : "l"(a), "l"(b)); }
__device__ __forceinline__ void unpack2(ull v, float& lo, float& hi) { asm("mov.b64 {%0,%1},%2;" : "=f"(lo), "=f"(hi) : "l"(v)); }

__device__ __forceinline__ void ldsm4(uint32_t& r0, uint32_t& r1, uint32_t& r2, uint32_t& r3, uint32_t a) {
    asm volatile("ldmatrix.sync.aligned.m8n8.x4.shared.b16 {%0,%1,%2,%3}, [%4];"
                 : "=r"(r0), "=r"(r1), "=r"(r2), "=r"(r3) : "r"(a));
}
__device__ __forceinline__ void mma16816(float* c, uint32_t a0, uint32_t a1, uint32_t a2, uint32_t a3,
                                         uint32_t b0, uint32_t b1) {
    asm volatile("mma.sync.aligned.m16n8k16.row.col.f32.f16.f16.f32 "
                 "{%0,%1,%2,%3}, {%4,%5,%6,%7}, {%8,%9}, {%0,%1,%2,%3};"
                 : "+f"(c[0]), "+f"(c[1]), "+f"(c[2]), "+f"(c[3])
                 : "r"(a0), "r"(a1), "r"(a2), "r"(a3), "r"(b0), "r"(b1));
}

__global__ void __launch_bounds__(NT, 1) fm_logp_kernel(
    const float* __restrict__ actions, const float* __restrict__ feats,
    const float* __restrict__ W1, const float* __restrict__ b1,
    const float* __restrict__ W2, const float* __restrict__ b2g,
    const float* __restrict__ W3g, const float* __restrict__ b3g,
    const float* __restrict__ eps, float* __restrict__ out)
{
    extern __shared__ char smraw[];
    const uint32_t base0 = cvta_smem(smraw);
    const uint32_t smb = (base0 + 1023u) & ~1023u;
    char* smc = smraw + (smb - base0);

    float* vp_s = (float*)(smc + OFF_VP);
    float* jp_s = (float*)(smc + OFF_JP);
    float* w3s  = (float*)(smc + OFF_W3);
    float* b2s  = (float*)(smc + OFF_B2);
    float* a_s  = (float*)(smc + OFF_AS);
    float* e_s  = (float*)(smc + OFF_ES);
    float* di_s = (float*)(smc + OFF_DI);

    const int tid  = threadIdx.x;
    const int lane = tid & 31;
    const int warp = tid >> 5;
    const int row0 = blockIdx.x * TB;

    // ================= setup: c_base = feats @ W1[8:264] + b1 (fp32, one-time) =================
    {
        float* featss = (float*)(smc + OFF_W2T);  // [64][260]
        float* wstp   = (float*)(smc + OFF_VP);   // [16][256] (spans VP+JP)
        float* cb32   = (float*)(smc + OFF_X);    // [64][256]

        for (int idx = tid; idx < TB * Hdim; idx += NT)
            featss[(idx >> 8) * 260 + (idx & 255)] = feats[row0 * Hdim + idx];
        if (tid < TB * Adim) a_s[tid] = actions[row0 * Adim + tid];
        if (tid < TB) di_s[tid] = 0.0f;
        __syncthreads();

        const int wr0 = warp * 4, jb = lane * 8;
        ull acc[4][4];
        #pragma unroll
        for (int r = 0; r < 4; r++)
            #pragma unroll
            for (int c = 0; c < 4; c++) acc[r][c] = 0ull;

        for (int kb = 0; kb < Hdim; kb += 16) {
            __syncthreads();
            {
                int i = tid;      int rr = i >> 6, cf = (i & 63) << 2;
                *(float4*)&wstp[rr * 256 + cf] = *(const float4*)&W1[(Adim + kb + rr) * Hdim + cf];
                i = tid + NT;     rr = i >> 6;  cf = (i & 63) << 2;
                *(float4*)&wstp[rr * 256 + cf] = *(const float4*)&W1[(Adim + kb + rr) * Hdim + cf];
            }
            __syncthreads();
            #pragma unroll
            for (int kk = 0; kk < 16; kk += 4) {
                float hb[4][4];
                #pragma unroll
                for (int r = 0; r < 4; r++)
                    *(float4*)hb[r] = *(const float4*)&featss[(wr0 + r) * 260 + kb + kk];
                #pragma unroll
                for (int j = 0; j < 4; j++) {
                    const float* wr_ = &wstp[(kk + j) * 256 + jb];
                    ulonglong2 w01 = *(const ulonglong2*)wr_;
                    ulonglong2 w23 = *(const ulonglong2*)(wr_ + 4);
                    #pragma unroll
                    for (int r = 0; r < 4; r++) {
                        ull hp = pack2(hb[r][j]);
                        fma2(acc[r][0], hp, w01.x); fma2(acc[r][1], hp, w01.y);
                        fma2(acc[r][2], hp, w23.x); fma2(acc[r][3], hp, w23.y);
                    }
                }
            }
        }
        __syncthreads();
        float4 bb0 = *(const float4*)&b1[jb];
        float4 bb1 = *(const float4*)&b1[jb + 4];
        #pragma unroll
        for (int r = 0; r < 4; r++) {
            float o[8];
            unpack2(acc[r][0], o[0], o[1]); unpack2(acc[r][1], o[2], o[3]);
            unpack2(acc[r][2], o[4], o[5]); unpack2(acc[r][3], o[6], o[7]);
            o[0] += bb0.x; o[1] += bb0.y; o[2] += bb0.z; o[3] += bb0.w;
            o[4] += bb1.x; o[5] += bb1.y; o[6] += bb1.z; o[7] += bb1.w;
            *(float4*)&cb32[(wr0 + r) * 256 + jb]     = make_float4(o[0], o[1], o[2], o[3]);
            *(float4*)&cb32[(wr0 + r) * 256 + jb + 4] = make_float4(o[4], o[5], o[6], o[7]);
        }
        __syncthreads();
    }

    // ---- per-thread persistent state ----
    const int c2 = (tid & 127) * 2;   // phase-A column pair
    const int rh = tid >> 7;          // 0..3 : rows rh, rh+4, ...
    float2 cb[16];
    {
        const float* cb32 = (const float*)(smc + OFF_X);
        #pragma unroll
        for (int j = 0; j < 16; j++)
            cb[j] = *(const float2*)&cb32[(rh + 4 * j) * 256 + c2];
    }
    __syncthreads();   // X region free for the f16 tile now

    float w1a2[Adim][2], w1t2[2];
    #pragma unroll
    for (int k = 0; k < Adim; k++) {
        w1a2[k][0] = W1[k * Hdim + c2];
        w1a2[k][1] = W1[k * Hdim + c2 + 1];
    }
    w1t2[0] = W1[(Adim + Hdim) * Hdim + c2];
    w1t2[1] = W1[(Adim + Hdim) * Hdim + c2 + 1];
    const float b3_r = b3g[tid & 7];

    // ---- W2^T f16 swizzled [n][k], W3, b2 into smem ----
    for (int idx = tid; idx < Hdim * Hdim; idx += NT) {
        int k = idx >> 8, n = idx & 255;
        uint32_t byte = (uint32_t)((((n >> 3) + ((k >> 6) << 5)) << 10) + ((n & 7) << 7) + ((k & 63) << 1));
        *(__half*)(smc + OFF_W2T + swz(byte)) = __float2half_rn(W2[idx]);
    }
    for (int idx = tid; idx < Hdim * Adim; idx += NT) w3s[idx] = W3g[idx];
    if (tid < Hdim) b2s[tid] = b2g[tid];
    __syncthreads();

    // ---- warp tiling + ldmatrix base offsets ----
    const int m0 = (warp >> 2) * 32;        // X row base (32 rows)
    const int n0 = (warp & 3) * 64;         // output col base (64 cols)
    const int rowA = m0 + ((lane >> 3) & 1) * 8 + (lane & 7);
    const int kA0  = (lane >> 4) * 8;
    uint32_t aoff0 = smb + OFF_X + (((uint32_t)(rowA >> 3)) << 10) + (((uint32_t)(rowA & 7)) << 7)
                   + ((uint32_t)kA0 << 1);
    aoff0 ^= ((uint32_t)(rowA & 7)) << 4;
    const int nB  = n0 + ((lane >> 4) & 1) * 8 + (lane & 7);
    const int kB0 = ((lane >> 3) & 1) * 8;
    uint32_t boff0 = smb + OFF_W2T + (((uint32_t)(nB >> 3)) << 10) + (((uint32_t)(nB & 7)) << 7)
                   + ((uint32_t)kB0 << 1);
    boff0 ^= ((uint32_t)(nB & 7)) << 4;

    const bool zrow = ((lane >> 2) & 1) == 0;          // even X row => h (value) row
    const int  br0  = (m0 >> 1) + ((lane >> 2) >> 1);  // batch row base for epilogue slots
    const float4* pa = (const float4*)a_s;
    const float4* pe = (const float4*)e_s;

    // ================= 50 reverse-Euler steps =================
    for (int step = 0; step < NSTEPS; step++) {
        const float tcur = 1.0f - (float)step * DTC;

        __syncthreads();
        e_s[tid] = eps[(size_t)step * Bsz * Adim + row0 * Adim + tid];
        __syncthreads();

        // ---- phase A: layer-1 value+tangent, silu, write X f16 (rows 2r=h, 2r+1=g) ----
        #pragma unroll
        for (int j = 0; j < 16; j++) {
            const int r = rh + 4 * j;
            float4 a0 = pa[2 * r], a1 = pa[2 * r + 1];
            float4 e0 = pe[2 * r], e1 = pe[2 * r + 1];
            float av[8] = {a0.x, a0.y, a0.z, a0.w, a1.x, a1.y, a1.z, a1.w};
            float ev[8] = {e0.x, e0.y, e0.z, e0.w, e1.x, e1.y, e1.z, e1.w};
            float z0 = cb[j].x + tcur * w1t2[0];
            float z1 = cb[j].y + tcur * w1t2[1];
            float d0 = 0.f, d1 = 0.f;
            #pragma unroll
            for (int k = 0; k < Adim; k++) {
                z0 += av[k] * w1a2[k][0];  z1 += av[k] * w1a2[k][1];
                d0 += ev[k] * w1a2[k][0];  d1 += ev[k] * w1a2[k][1];
            }
            float s0 = 1.0f / (1.0f + __expf(-z0));
            float s1 = 1.0f / (1.0f + __expf(-z1));
            float h0 = z0 * s0, h1v = z1 * s1;
            float g0 = d0 * (s0 * (1.0f + z0 * (1.0f - s0)));
            float g1v = d1 * (s1 * (1.0f + z1 * (1.0f - s1)));
            *(__half2*)(smc + OFF_X + swz(xbyte(2 * r,     c2))) = __floats2half2_rn(h0, h1v);
            *(__half2*)(smc + OFF_X + swz(xbyte(2 * r + 1, c2))) = __floats2half2_rn(g0, g1v);
        }
        __syncthreads();

        // ---- GEMM: D[32x64 per warp] = X @ W2T^T via mma.sync m16n8k16 ----
        float acc[2][8][4];
        #pragma unroll
        for (int mt = 0; mt < 2; mt++)
            #pragma unroll
            for (int nt = 0; nt < 8; nt++)
                #pragma unroll
                for (int i = 0; i < 4; i++) acc[mt][nt][i] = 0.0f;

        #pragma unroll
        for (int kc = 0; kc < 16; kc++) {
            const uint32_t klo = ((uint32_t)(kc & 3)) << 5;
            uint32_t ka = (aoff0 + (((uint32_t)(kc >> 2)) << 14)) ^ klo;
            uint32_t a00, a01, a02, a03, a10, a11, a12, a13;
            ldsm4(a00, a01, a02, a03, ka);
            ldsm4(a10, a11, a12, a13, ka + 2048);   // rows +16
            uint32_t kb = (boff0 + (((uint32_t)(kc >> 2)) << 15)) ^ klo;
            #pragma unroll
            for (int p = 0; p < 4; p++) {
                uint32_t b0, b1, b2r, b3r;
                ldsm4(b0, b1, b2r, b3r, kb + (uint32_t)p * 2048);   // n-tiles 2p, 2p+1
                mma16816(acc[0][2 * p],     a00, a01, a02, a03, b0, b1);
                mma16816(acc[0][2 * p + 1], a00, a01, a02, a03, b2r, b3r);
                mma16816(acc[1][2 * p],     a10, a11, a12, a13, b0, b1);
                mma16816(acc[1][2 * p + 1], a10, a11, a12, a13, b2r, b3r);
            }
        }

        // ---- epilogue (registers): silu'(z2) pairing via shfl, project through W3 ----
        {
            float vj[4][8];
            #pragma unroll
            for (int s = 0; s < 4; s++)
                #pragma unroll
                for (int i = 0; i < 8; i++) vj[s][i] = 0.0f;

            #pragma unroll
            for (int nt = 0; nt < 8; nt++) {
                const int colb = n0 + nt * 8 + (lane & 3) * 2;
                const float b2a = b2s[colb], b2b = b2s[colb + 1];
                float ct[4][2];
                #pragma unroll
                for (int mt = 0; mt < 2; mt++) {
                    float v0 = acc[mt][nt][0], v1 = acc[mt][nt][1];
                    float v2 = acc[mt][nt][2], v3 = acc[mt][nt][3];
                    float z0 = v0 + b2a, z1 = v1 + b2b, z2 = v2 + b2a, z3 = v3 + b2b;
                    float s0 = 1.0f / (1.0f + __expf(-z0));
                    float s1 = 1.0f / (1.0f + __expf(-z1));
                    float s2 = 1.0f / (1.0f + __expf(-z2));
                    float s3 = 1.0f / (1.0f + __expf(-z3));
                    float dc0 = s0 * (1.0f + z0 * (1.0f - s0));
                    float dc1 = s1 * (1.0f + z1 * (1.0f - s1));
                    float dc2 = s2 * (1.0f + z2 * (1.0f - s2));
                    float dc3 = s3 * (1.0f + z3 * (1.0f - s3));
                    float r0 = __shfl_up_sync(0xffffffffu, dc0, 4);
                    float r1 = __shfl_up_sync(0xffffffffu, dc1, 4);
                    float r2 = __shfl_up_sync(0xffffffffu, dc2, 4);
                    float r3 = __shfl_up_sync(0xffffffffu, dc3, 4);
                    ct[mt * 2 + 0][0] = zrow ? z0 * s0 : v0 * r0;
                    ct[mt * 2 + 0][1] = zrow ? z1 * s1 : v1 * r1;
                    ct[mt * 2 + 1][0] = zrow ? z2 * s2 : v2 * r2;
                    ct[mt * 2 + 1][1] = zrow ? z3 * s3 : v3 * r3;
                }
                float4 wa0 = *(const float4*)&w3s[colb * 8];
                float4 wa1 = *(const float4*)&w3s[colb * 8 + 4];
                float4 wb0 = *(const float4*)&w3s[(colb + 1) * 8];
                float4 wb1 = *(const float4*)&w3s[(colb + 1) * 8 + 4];
                #pragma unroll
                for (int s = 0; s < 4; s++) {
                    vj[s][0] += ct[s][0] * wa0.x + ct[s][1] * wb0.x;
                    vj[s][1] += ct[s][0] * wa0.y + ct[s][1] * wb0.y;
                    vj[s][2] += ct[s][0] * wa0.z + ct[s][1] * wb0.z;
                    vj[s][3] += ct[s][0] * wa0.w + ct[s][1] * wb0.w;
                    vj[s][4] += ct[s][0] * wa1.x + ct[s][1] * wb1.x;
                    vj[s][5] += ct[s][0] * wa1.y + ct[s][1] * wb1.y;
                    vj[s][6] += ct[s][0] * wa1.z + ct[s][1] * wb1.z;
                    vj[s][7] += ct[s][0] * wa1.w + ct[s][1] * wb1.w;
                }
            }
            // reduce over the 4 lanes of each quad (same row, different col pairs)
            #pragma unroll
            for (int s = 0; s < 4; s++)
                #pragma unroll
                for (int i = 0; i < 8; i++) {
                    vj[s][i] += __shfl_xor_sync(0xffffffffu, vj[s][i], 1);
                    vj[s][i] += __shfl_xor_sync(0xffffffffu, vj[s][i], 2);
                }
            if ((lane & 3) == 0) {
                float* dst = (zrow ? vp_s : jp_s) + (warp & 3) * 512;
                #pragma unroll
                for (int s = 0; s < 4; s++) {
                    const int row = br0 + (s & 1) * 4 + (s >> 1) * 8;
                    *(float4*)&dst[row * 8]     = make_float4(vj[s][0], vj[s][1], vj[s][2], vj[s][3]);
                    *(float4*)&dst[row * 8 + 4] = make_float4(vj[s][4], vj[s][5], vj[s][6], vj[s][7]);
                }
            }
        }
        __syncthreads();

        // ---- update: reduce 4 n-groups, Euler step, divergence integral ----
        {
            const int ur = tid >> 3, ui = tid & 7;
            float v = b3_r, jv = 0.0f;
            #pragma unroll
            for (int g = 0; g < 4; g++) {
                v  += vp_s[g * 512 + ur * 8 + ui];
                jv += jp_s[g * 512 + ur * 8 + ui];
            }
            float dp = jv * e_s[ur * 8 + ui];
            dp += __shfl_xor_sync(0xffffffffu, dp, 1);
            dp += __shfl_xor_sync(0xffffffffu, dp, 2);
            dp += __shfl_xor_sync(0xffffffffu, dp, 4);
            a_s[ur * 8 + ui] -= v * DTC;
            if (ui == 0) di_s[ur] += dp * DTC;
        }
    }

    // ================= output =================
    __syncthreads();
    if (tid < TB) {
        float s2 = 0.0f;
        #pragma unroll
        for (int i = 0; i < Adim; i++) {
            float av = a_s[tid * Adim + i];
            s2 += av * av;
        }
        out[row0 + tid] = -0.5f * (s2 + (float)Adim * 1.8378770664093453f) - di_s[tid];
    }
}

extern "C" void kernel_launch(void* const* d_in, const int* in_sizes, int n_in,
                              void* d_out, int out_size) {
    (void)in_sizes; (void)n_in; (void)out_size;
    cudaFuncSetAttribute(fm_logp_kernel,
                         cudaFuncAttributeMaxDynamicSharedMemorySize, SMEM_BYTES);
    fm_logp_kernel<<<Bsz / TB, NT, SMEM_BYTES>>>(
        (const float*)d_in[0], (const float*)d_in[1], (const float*)d_in[2],
        (const float*)d_in[3], (const float*)d_in[4], (const float*)d_in[5],
        (const float*)d_in[6], (const float*)d_in[7], (const float*)d_in[8],
        (float*)d_out);
}